// round 15
// baseline (speedup 1.0000x reference)
#include <cuda_runtime.h>
#include <cuda_bf16.h>
#include <cstdint>

// ---------------------------------------------------------------------------
// Mamba block forward.  B=2, L=2048, d_model=512, d_inner=1024, d_state=16,
// dt_rank=32, d_conv=4.
// Launches: 1-3 cvt_k      x / in_proj_w / out_proj_w -> tf32
//           4 gemm_tf<1,128> in_proj (tf32 mma, ldmatrix, early fill) [profiled]
//           5 conv_xproj   conv+silu + x_proj fused
//           6 gemm_nt4     dt_proj + softplus -> delta_t
//           7-9 scan A/B/C chunked selective scan (thread-per-channel)
//          10 gemm_tf<6,64> out_proj
// ---------------------------------------------------------------------------

#define BATCH    2
#define SEQLEN   2048
#define DMODEL   512
#define DINNER   1024
#define DSTATE   16
#define DTRANK   32
#define DCONV    4
#define MROWS    (BATCH * SEQLEN)        // 4096
#define NCHAN    (BATCH * DINNER)        // 2048 scan channels
#define TCHUNK   32                      // scan chunks along L
#define CLEN     (SEQLEN / TCHUNK)       // 64 steps per chunk

// Scratch (device-global; no runtime allocation allowed)
__device__ float g_xz[(size_t)MROWS * 2 * DINNER];    // [4096, 2048]  xs | z
__device__ float g_xst[(size_t)NCHAN * SEQLEN];       // xs transposed [ch][l]
__device__ float g_zt[(size_t)NCHAN * SEQLEN];        // z transposed [ch][l]
__device__ float g_xdbl[(size_t)MROWS * 64];          // [4096, 64]
__device__ float g_deltat[(size_t)NCHAN * SEQLEN];    // delta transposed [ch][l]
__device__ float g_y[(size_t)MROWS * DINNER];         // scan output (tf32-rounded)
__device__ uint32_t g_w6tf[(size_t)DMODEL * DINNER];  // out_proj_w in tf32
__device__ uint32_t g_x1tf[(size_t)MROWS * DMODEL];   // x in tf32
__device__ uint32_t g_w1tf[(size_t)2 * DINNER * DMODEL]; // in_proj_w in tf32
__device__ float g_hend[(size_t)TCHUNK * NCHAN * DSTATE];
__device__ float g_decay[(size_t)TCHUNK * NCHAN * DSTATE];
__device__ float g_h0[(size_t)TCHUNK * NCHAN * DSTATE];

// ---------------------------------------------------------------------------
__device__ __forceinline__ uint32_t f2tf32(float f) {
    uint32_t r;
    asm("cvt.rna.tf32.f32 %0, %1;" : "=r"(r) : "f"(f));
    return r;
}

__device__ __forceinline__ void mma_tf32(float c[4], const uint32_t a[4],
                                         uint32_t b0, uint32_t b1) {
    asm volatile(
        "mma.sync.aligned.m16n8k8.row.col.f32.tf32.tf32.f32 "
        "{%0,%1,%2,%3}, {%4,%5,%6,%7}, {%8,%9}, {%0,%1,%2,%3};"
        : "+f"(c[0]), "+f"(c[1]), "+f"(c[2]), "+f"(c[3])
        : "r"(a[0]), "r"(a[1]), "r"(a[2]), "r"(a[3]), "r"(b0), "r"(b1));
}

__device__ __forceinline__ void ldsm_x4(uint32_t r[4], uint32_t addr) {
    asm volatile(
        "ldmatrix.sync.aligned.m8n8.x4.shared.b16 {%0,%1,%2,%3}, [%4];"
        : "=r"(r[0]), "=r"(r[1]), "=r"(r[2]), "=r"(r[3]) : "r"(addr));
}

__device__ __forceinline__ void cp16(uint32_t dst_smem, const void* src) {
    asm volatile("cp.async.cg.shared.global [%0], [%1], 16;\n"
                 :: "r"(dst_smem), "l"(src));
}

// ---------------------------------------------------------------------------
// Prepass: WHICH 0: x -> g_x1tf, 1: in_proj_w -> g_w1tf, 2: out_proj_w -> g_w6tf
// ---------------------------------------------------------------------------
template <int WHICH>
__global__ void __launch_bounds__(256)
cvt_k(const float* __restrict__ src)
{
    uint32_t* dst = (WHICH == 0) ? g_x1tf : (WHICH == 1) ? g_w1tf : g_w6tf;
    const size_t i4 = ((size_t)blockIdx.x * 256 + threadIdx.x) * 4;
    float4 v = *(const float4*)&src[i4];
    uint4 p;
    p.x = f2tf32(v.x); p.y = f2tf32(v.y);
    p.z = f2tf32(v.z); p.w = f2tf32(v.w);
    *(uint4*)&dst[i4] = p;
}

// ---------------------------------------------------------------------------
// tf32 mma NT GEMM, BK=32 SW128 swizzle, 3-stage cp.async, ldmatrix fragments.
// Fill for chunk c+2 is issued right after the barrier, BEFORE compute(c):
// safe because all warps past the barrier finished compute(c-1), the only
// reader of stage (c+2)%3.  Fill addressing fully hoisted.
//   STAGE 1 (BN=128): A=g_x1tf, W=g_w1tf, C=g_xz, K=512,  ldc=2048
//   STAGE 6 (BN=64):  A=g_y,    W=g_w6tf, C=out,  K=1024, ldc=512
// ---------------------------------------------------------------------------
#define GTF_SMEM(BN) (1024 + 3 * ((128 + (BN)) * 128))

template <int STAGE, int BN>
__global__ void __launch_bounds__(256)
gemm_tf(float* __restrict__ Cp)
{
    constexpr int K   = (STAGE == 1) ? DMODEL : DINNER;
    constexpr int ldc = (STAGE == 1) ? 2 * DINNER : DMODEL;
    constexpr int NC  = K / 32;                        // 32-K chunks
    constexpr int JN  = BN / 16;                       // n atoms per warp
    constexpr int J2  = JN / 2;                        // ldmatrix pairs
    constexpr int NBT = BN / 32;                       // B row-tiles per fill
    constexpr int ASZ = 128 * 32;                      // u32 per A stage
    constexpr int BSZ = BN * 32;                       // u32 per B stage

    const uint32_t* Ab = (STAGE == 1) ? g_x1tf : (const uint32_t*)g_y;
    const uint32_t* Wb = (STAGE == 1) ? g_w1tf : g_w6tf;
    float* C = (STAGE == 1) ? g_xz : Cp;

    extern __shared__ char dsm[];
    uint32_t* sbase = (uint32_t*)(((uintptr_t)dsm + 1023) & ~(uintptr_t)1023);
    uint32_t* const SA = sbase;                        // 3 x ASZ
    uint32_t* const SB = sbase + 3 * ASZ;              // 3 x BSZ
    const uint32_t saB = (uint32_t)__cvta_generic_to_shared(SA);
    const uint32_t sbB = (uint32_t)__cvta_generic_to_shared(SB);

    const int tid = threadIdx.x;
    const int lane = tid & 31;
    const int wid = tid >> 5;
    const int wm = (wid & 3) * 32;
    const int wn = (wid >> 2) * (BN / 2);
    const int g  = lane >> 2;
    const int tg = lane & 3;
    const int m0 = blockIdx.y * 128;
    const int n0 = blockIdx.x * BN;

    // ldmatrix per-lane addressing
    const int mi = lane >> 3;
    const int rr = lane & 7;
    uint32_t aRow[2];
#pragma unroll
    for (int i = 0; i < 2; i++)
        aRow[i] = (uint32_t)((wm + i * 16 + ((mi & 1) << 3) + rr) * 32);
    const int qaB = mi >> 1;
    uint32_t bRow[J2];
#pragma unroll
    for (int j2 = 0; j2 < J2; j2++)
        bRow[j2] = (uint32_t)((wn + j2 * 16 + ((mi >> 1) << 3) + rr) * 32);
    const int qbB = mi & 1;

    // hoisted fill addressing: per-thread row ptrs + swizzled smem offsets
    const int fcs = tid & 7;
    const int fr0 = tid >> 3;                          // 0..31
    const uint32_t* gA[4];
    uint32_t offA[4];
#pragma unroll
    for (int it = 0; it < 4; it++) {
        const int r = fr0 + it * 32;
        gA[it] = Ab + (size_t)(m0 + r) * K + fcs * 4;
        offA[it] = (uint32_t)(r * 32 + ((fcs ^ (r & 7)) << 2)) * 4;
    }
    const uint32_t* gB[NBT];
    uint32_t offB[NBT];
#pragma unroll
    for (int it = 0; it < NBT; it++) {
        const int r = fr0 + it * 32;
        gB[it] = Wb + (size_t)(n0 + r) * K + fcs * 4;
        offB[it] = (uint32_t)(r * 32 + ((fcs ^ (r & 7)) << 2)) * 4;
    }

    auto fill = [&](int st, int kc) {
        const uint32_t sa = saB + (uint32_t)(st * ASZ * 4);
        const uint32_t sb = sbB + (uint32_t)(st * BSZ * 4);
        const int k0 = kc * 32;
#pragma unroll
        for (int it = 0; it < 4; it++)
            cp16(sa + offA[it], gA[it] + k0);
#pragma unroll
        for (int it = 0; it < NBT; it++)
            cp16(sb + offB[it], gB[it] + k0);
    };

    float c[2][JN][4];
#pragma unroll
    for (int i = 0; i < 2; i++)
#pragma unroll
        for (int j = 0; j < JN; j++)
#pragma unroll
            for (int r = 0; r < 4; r++) c[i][j][r] = 0.f;

    fill(0, 0); asm volatile("cp.async.commit_group;\n" ::);
    fill(1, 1); asm volatile("cp.async.commit_group;\n" ::);

#pragma unroll 1
    for (int cchunk = 0; cchunk < NC; cchunk++) {
        const int s = cchunk % 3;
        if (cchunk + 1 < NC) asm volatile("cp.async.wait_group 1;\n" ::);
        else                 asm volatile("cp.async.wait_group 0;\n" ::);
        __syncthreads();

        // early prefetch: overlap cp.async with this chunk's compute
        if (cchunk + 2 < NC) {
            fill((cchunk + 2) % 3, cchunk + 2);
            asm volatile("cp.async.commit_group;\n" ::);
        }

        const uint32_t saS = saB + (uint32_t)(s * ASZ * 4);
        const uint32_t sbS = sbB + (uint32_t)(s * BSZ * 4);
#pragma unroll
        for (int kk = 0; kk < 4; kk++) {               // 4 x K=8 per chunk
            const int q0 = kk * 2;
            uint32_t a[2][4];
#pragma unroll
            for (int i = 0; i < 2; i++) {
                const uint32_t q = (uint32_t)(q0 + qaB);
                ldsm_x4(a[i], saS + (aRow[i] + (((q ^ (uint32_t)rr)) << 2)) * 4);
            }
            uint32_t bf[JN][2];
#pragma unroll
            for (int j2 = 0; j2 < J2; j2++) {
                const uint32_t q = (uint32_t)(q0 + qbB);
                uint32_t t[4];
                ldsm_x4(t, sbS + (bRow[j2] + (((q ^ (uint32_t)rr)) << 2)) * 4);
                bf[2 * j2][0] = t[0]; bf[2 * j2][1] = t[1];
                bf[2 * j2 + 1][0] = t[2]; bf[2 * j2 + 1][1] = t[3];
            }
#pragma unroll
            for (int j = 0; j < JN; j++) {
                mma_tf32(c[0][j], a[0], bf[j][0], bf[j][1]);
                mma_tf32(c[1][j], a[1], bf[j][0], bf[j][1]);
            }
        }
    }

    // epilogue
#pragma unroll
    for (int i = 0; i < 2; i++) {
        const int mrow0 = m0 + wm + i * 16 + g;
#pragma unroll
        for (int j = 0; j < JN; j++) {
            const int ncol = n0 + wn + j * 8 + 2 * tg;
            *(float2*)&C[(size_t)mrow0 * ldc + ncol] =
                make_float2(c[i][j][0], c[i][j][1]);
            *(float2*)&C[(size_t)(mrow0 + 8) * ldc + ncol] =
                make_float2(c[i][j][2], c[i][j][3]);
        }
    }
}

// ---------------------------------------------------------------------------
// Stage 2+3 fused: conv1d+SiLU, x_proj GEMM; writes xs_t and z_t transposed.
// ---------------------------------------------------------------------------
__global__ void __launch_bounds__(256)
conv_xproj(const float* __restrict__ conv_w,
           const float* __restrict__ conv_b,
           const float* __restrict__ x_proj_w)
{
    __shared__ float sxs[32][68];
    __shared__ float sw[64][68];
    __shared__ float sz[32][68];

    const int tid = threadIdx.x;
    const int bl0 = blockIdx.x * 32;
    const int b   = bl0 >> 11;
    const int l0  = bl0 & 2047;
    const int tx = tid & 15;
    const int ty = tid >> 4;

    float acc[2][4];
#pragma unroll
    for (int i = 0; i < 2; i++)
#pragma unroll
        for (int j = 0; j < 4; j++) acc[i][j] = 0.f;

#pragma unroll 1
    for (int d0 = 0; d0 < DINNER; d0 += 64) {
        __syncthreads();
#pragma unroll
        for (int it = 0; it < 4; it++) {
            const int idx = tid + it * 256;
            const int e = idx >> 4, c4 = (idx & 15) * 4;
            *(float4*)&sw[e][c4] =
                *(const float4*)&x_proj_w[(size_t)e * DINNER + d0 + c4];
        }
#pragma unroll
        for (int it = 0; it < 8; it++) {
            const int idx = tid + it * 256;
            const int r = idx >> 6, dc = idx & 63;
            const int bl = bl0 + r;
            const int l = bl & (SEQLEN - 1);
            const int d = d0 + dc;
            float a = conv_b[d];
#pragma unroll
            for (int j = 0; j < DCONV; j++) {
                const int ls = l - (DCONV - 1) + j;
                if (ls >= 0)
                    a = fmaf(g_xz[(size_t)(bl - (DCONV - 1) + j) * (2 * DINNER) + d],
                             conv_w[d * DCONV + j], a);
            }
            sxs[r][dc] = a / (1.f + __expf(-a));     // SiLU
            sz[r][dc] = g_xz[(size_t)bl * (2 * DINNER) + DINNER + d];
        }
        __syncthreads();
        {
            const int dloc = tid >> 2;
            const int lq = (tid & 3) * 8;
            const size_t row = (size_t)(b * DINNER + d0 + dloc) * SEQLEN + l0 + lq;
            float4 v0, v1;
            v0.x = sxs[lq + 0][dloc]; v0.y = sxs[lq + 1][dloc];
            v0.z = sxs[lq + 2][dloc]; v0.w = sxs[lq + 3][dloc];
            v1.x = sxs[lq + 4][dloc]; v1.y = sxs[lq + 5][dloc];
            v1.z = sxs[lq + 6][dloc]; v1.w = sxs[lq + 7][dloc];
            *(float4*)&g_xst[row] = v0;
            *(float4*)&g_xst[row + 4] = v1;
            v0.x = sz[lq + 0][dloc]; v0.y = sz[lq + 1][dloc];
            v0.z = sz[lq + 2][dloc]; v0.w = sz[lq + 3][dloc];
            v1.x = sz[lq + 4][dloc]; v1.y = sz[lq + 5][dloc];
            v1.z = sz[lq + 6][dloc]; v1.w = sz[lq + 7][dloc];
            *(float4*)&g_zt[row] = v0;
            *(float4*)&g_zt[row + 4] = v1;
        }
#pragma unroll
        for (int kk = 0; kk < 64; kk++) {
            float ar[2], br[4];
#pragma unroll
            for (int i = 0; i < 2; i++) ar[i] = sxs[ty * 2 + i][kk];
#pragma unroll
            for (int j = 0; j < 4; j++) br[j] = sw[tx * 4 + j][kk];
#pragma unroll
            for (int i = 0; i < 2; i++)
#pragma unroll
                for (int j = 0; j < 4; j++)
                    acc[i][j] = fmaf(ar[i], br[j], acc[i][j]);
        }
    }

#pragma unroll
    for (int i = 0; i < 2; i++)
#pragma unroll
        for (int j = 0; j < 4; j++)
            g_xdbl[(size_t)(bl0 + ty * 2 + i) * 64 + tx * 4 + j] = acc[i][j];
}

// ---------------------------------------------------------------------------
// Stage 4: dt_proj + softplus -> delta_t[ch][l] (transposed write).
// ---------------------------------------------------------------------------
__global__ void __launch_bounds__(256)
gemm_nt4(const float* __restrict__ W, const float* __restrict__ bias)
{
    constexpr int BM = 64, BN = 64, BK = 16;
    constexpr int lda = 64, ldw = DTRANK, K = DTRANK;
    const float* A = g_xdbl;

    __shared__ float As[BK][BM];
    __shared__ float Bs[BK][BN];

    const int tid = threadIdx.x;
    const int m0 = blockIdx.y * BM;
    const int n0 = blockIdx.x * BN;
    const int tx = tid & 15;
    const int ty = tid >> 4;
    const int lrow = tid >> 2;
    const int lc4 = (tid & 3) * 4;

    float acc[4][4];
#pragma unroll
    for (int i = 0; i < 4; i++)
#pragma unroll
        for (int j = 0; j < 4; j++) acc[i][j] = 0.f;

    const float* Arow = A + (size_t)(m0 + lrow) * lda + lc4;
    const float* Wrow = W + (size_t)(n0 + lrow) * ldw + lc4;

#pragma unroll 1
    for (int k0 = 0; k0 < K; k0 += BK) {
        float4 av = *(const float4*)(Arow + k0);
        float4 wv = *(const float4*)(Wrow + k0);
        __syncthreads();
        As[lc4 + 0][lrow] = av.x; As[lc4 + 1][lrow] = av.y;
        As[lc4 + 2][lrow] = av.z; As[lc4 + 3][lrow] = av.w;
        Bs[lc4 + 0][lrow] = wv.x; Bs[lc4 + 1][lrow] = wv.y;
        Bs[lc4 + 2][lrow] = wv.z; Bs[lc4 + 3][lrow] = wv.w;
        __syncthreads();
#pragma unroll
        for (int kk = 0; kk < BK; kk++) {
            float4 a4 = *(const float4*)&As[kk][ty * 4];
            float4 b4 = *(const float4*)&Bs[kk][tx * 4];
            float ar[4] = {a4.x, a4.y, a4.z, a4.w};
            float br[4] = {b4.x, b4.y, b4.z, b4.w};
#pragma unroll
            for (int i = 0; i < 4; i++)
#pragma unroll
                for (int j = 0; j < 4; j++)
                    acc[i][j] = fmaf(ar[i], br[j], acc[i][j]);
        }
    }

    const int b = m0 >> 11;
    const int lb = (m0 & 2047) + ty * 4;
#pragma unroll
    for (int j = 0; j < 4; j++) {
        const int n = n0 + tx * 4 + j;
        float sp[4];
#pragma unroll
        for (int i = 0; i < 4; i++) {
            float v = acc[i][j] + bias[n];
            sp[i] = (v > 20.f) ? v : log1pf(__expf(v));
        }
        *(float4*)&g_deltat[(size_t)(b * DINNER + n) * SEQLEN + lb] =
            make_float4(sp[0], sp[1], sp[2], sp[3]);
    }
}

// ---------------------------------------------------------------------------
// Scan phase A: thread-per-channel; all 16 states in registers.
// ---------------------------------------------------------------------------
__global__ void __launch_bounds__(128)
scan_phaseA(const float* __restrict__ A_log)
{
    const int tid = threadIdx.x;
    const int ch = blockIdx.x * 128 + tid;     // global channel
    const int t  = blockIdx.y;
    const int b  = ch >> 10;
    const int d  = ch & (DINNER - 1);

    float A_dn[DSTATE];
#pragma unroll
    for (int q = 0; q < 4; q++) {
        float4 a4 = *(const float4*)&A_log[d * DSTATE + q * 4];
        A_dn[q * 4 + 0] = -__expf(a4.x);
        A_dn[q * 4 + 1] = -__expf(a4.y);
        A_dn[q * 4 + 2] = -__expf(a4.z);
        A_dn[q * 4 + 3] = -__expf(a4.w);
    }

    const float* dl = g_deltat + (size_t)ch * SEQLEN + t * CLEN;
    const float* us = g_xst    + (size_t)ch * SEQLEN + t * CLEN;
    const float* xb = g_xdbl + ((size_t)b * SEQLEN + t * CLEN) * 64 + 32;

    float h[DSTATE];
#pragma unroll
    for (int n = 0; n < DSTATE; n++) h[n] = 0.f;
    float sdt = 0.f;

#pragma unroll 1
    for (int l4 = 0; l4 < CLEN; l4 += 4) {
        const float4 d4 = *(const float4*)(dl + l4);
        const float4 u4 = *(const float4*)(us + l4);
        const float dts[4] = {d4.x, d4.y, d4.z, d4.w};
        const float uus[4] = {u4.x, u4.y, u4.z, u4.w};
#pragma unroll
        for (int j = 0; j < 4; j++) {
            const float4* Bp = (const float4*)(xb + (size_t)(l4 + j) * 64);
            float Bv[DSTATE];
#pragma unroll
            for (int q = 0; q < 4; q++) {
                float4 v = Bp[q];
                Bv[q * 4 + 0] = v.x; Bv[q * 4 + 1] = v.y;
                Bv[q * 4 + 2] = v.z; Bv[q * 4 + 3] = v.w;
            }
            const float dt = dts[j];
            const float dtu = dt * uus[j];
            sdt += dt;
#pragma unroll
            for (int n = 0; n < DSTATE; n++) {
                const float dA = __expf(dt * A_dn[n]);
                h[n] = fmaf(dA, h[n], dtu * Bv[n]);
            }
        }
    }

    float* he = g_hend  + ((size_t)t * NCHAN + ch) * DSTATE;
    float* de = g_decay + ((size_t)t * NCHAN + ch) * DSTATE;
#pragma unroll
    for (int q = 0; q < 4; q++)
        *(float4*)(he + q * 4) =
            make_float4(h[q * 4], h[q * 4 + 1], h[q * 4 + 2], h[q * 4 + 3]);
#pragma unroll
    for (int q = 0; q < 4; q++) {
        float4 v;
        v.x = __expf(sdt * A_dn[q * 4 + 0]);
        v.y = __expf(sdt * A_dn[q * 4 + 1]);
        v.z = __expf(sdt * A_dn[q * 4 + 2]);
        v.w = __expf(sdt * A_dn[q * 4 + 3]);
        *(float4*)(de + q * 4) = v;
    }
}

// ---------------------------------------------------------------------------
// Scan phase B: compose chunk states serially over T chunks.
// ---------------------------------------------------------------------------
__global__ void __launch_bounds__(256)
scan_phaseB()
{
    const int id = blockIdx.x * 256 + threadIdx.x;   // 0..NCHAN*DSTATE-1
    float h = 0.f;
#pragma unroll
    for (int t = 0; t < TCHUNK; t++) {
        const size_t o = (size_t)t * NCHAN * DSTATE + id;
        g_h0[o] = h;
        h = g_decay[o] * h + g_hend[o];
    }
}

// ---------------------------------------------------------------------------
// Scan phase C: thread-per-channel full scan from h0 -> y (no shfl).
// ---------------------------------------------------------------------------
__global__ void __launch_bounds__(128)
scan_phaseC(const float* __restrict__ A_log,
            const float* __restrict__ D_param)
{
    const int tid = threadIdx.x;
    const int ch = blockIdx.x * 128 + tid;
    const int t  = blockIdx.y;
    const int b  = ch >> 10;
    const int d  = ch & (DINNER - 1);

    float A_dn[DSTATE];
#pragma unroll
    for (int q = 0; q < 4; q++) {
        float4 a4 = *(const float4*)&A_log[d * DSTATE + q * 4];
        A_dn[q * 4 + 0] = -__expf(a4.x);
        A_dn[q * 4 + 1] = -__expf(a4.y);
        A_dn[q * 4 + 2] = -__expf(a4.z);
        A_dn[q * 4 + 3] = -__expf(a4.w);
    }
    const float Dd = D_param[d];

    const float* dl = g_deltat + (size_t)ch * SEQLEN + t * CLEN;
    const float* us = g_xst    + (size_t)ch * SEQLEN + t * CLEN;
    const float* zp = g_zt     + (size_t)ch * SEQLEN + t * CLEN;
    const float* xr = g_xdbl + ((size_t)b * SEQLEN + t * CLEN) * 64;
    float* yp = g_y + ((size_t)b * SEQLEN + t * CLEN) * DINNER + d;

    float h[DSTATE];
    {
        const float* h0 = g_h0 + ((size_t)t * NCHAN + ch) * DSTATE;
#pragma unroll
        for (int q = 0; q < 4; q++) {
            float4 v = *(const float4*)(h0 + q * 4);
            h[q * 4 + 0] = v.x; h[q * 4 + 1] = v.y;
            h[q * 4 + 2] = v.z; h[q * 4 + 3] = v.w;
        }
    }

#pragma unroll 1
    for (int l4 = 0; l4 < CLEN; l4 += 4) {
        const float4 d4 = *(const float4*)(dl + l4);
        const float4 u4 = *(const float4*)(us + l4);
        const float4 z4 = *(const float4*)(zp + l4);
        const float dts[4] = {d4.x, d4.y, d4.z, d4.w};
        const float uus[4] = {u4.x, u4.y, u4.z, u4.w};
        const float zzs[4] = {z4.x, z4.y, z4.z, z4.w};
#pragma unroll
        for (int j = 0; j < 4; j++) {
            const float4* Rp = (const float4*)(xr + (size_t)(l4 + j) * 64 + 32);
            float Bv[DSTATE], Cv[DSTATE];
#pragma unroll
            for (int q = 0; q < 4; q++) {
                float4 v = Rp[q];
                Bv[q * 4 + 0] = v.x; Bv[q * 4 + 1] = v.y;
                Bv[q * 4 + 2] = v.z; Bv[q * 4 + 3] = v.w;
                float4 w = Rp[q + 4];
                Cv[q * 4 + 0] = w.x; Cv[q * 4 + 1] = w.y;
                Cv[q * 4 + 2] = w.z; Cv[q * 4 + 3] = w.w;
            }
            const float dt = dts[j];
            const float dtu = dt * uus[j];
            float y = 0.f;
#pragma unroll
            for (int n = 0; n < DSTATE; n++) {
                const float dA = __expf(dt * A_dn[n]);
                h[n] = fmaf(dA, h[n], dtu * Bv[n]);
                y = fmaf(h[n], Cv[n], y);
            }
            const float z = zzs[j];
            const float sz = z / (1.f + __expf(-z));
            const float v = (y + uus[j] * Dd) * sz;
            yp[(size_t)(l4 + j) * DINNER] = __uint_as_float(f2tf32(v));
        }
    }
}

// ---------------------------------------------------------------------------
extern "C" void kernel_launch(void* const* d_in, const int* in_sizes, int n_in,
                              void* d_out, int out_size)
{
    const float* x          = (const float*)d_in[0];
    const float* in_proj_w  = (const float*)d_in[1];
    const float* conv_w     = (const float*)d_in[2];
    const float* conv_b     = (const float*)d_in[3];
    const float* x_proj_w   = (const float*)d_in[4];
    const float* dt_proj_w  = (const float*)d_in[5];
    const float* dt_proj_b  = (const float*)d_in[6];
    const float* A_log      = (const float*)d_in[7];
    const float* D_param    = (const float*)d_in[8];
    const float* out_proj_w = (const float*)d_in[9];
    float* out = (float*)d_out;

    cudaFuncSetAttribute((const void*)gemm_tf<1, 128>,
                         cudaFuncAttributeMaxDynamicSharedMemorySize, GTF_SMEM(128));
    cudaFuncSetAttribute((const void*)gemm_tf<6, 64>,
                         cudaFuncAttributeMaxDynamicSharedMemorySize, GTF_SMEM(64));

    // 1-3) tf32 prepasses
    cvt_k<0><<<(MROWS * DMODEL) / 1024, 256>>>(x);
    cvt_k<1><<<(2 * DINNER * DMODEL) / 1024, 256>>>(in_proj_w);
    cvt_k<2><<<(DMODEL * DINNER) / 1024, 256>>>(out_proj_w);

    // 4) in_proj (tf32 mma, ldmatrix, early fill) -> g_xz  [capture slot]
    gemm_tf<1, 128><<<dim3(2 * DINNER / 128, MROWS / 128), 256, GTF_SMEM(128)>>>(nullptr);

    // 5) conv+silu fused with x_proj -> g_xst, g_zt, g_xdbl
    conv_xproj<<<MROWS / 32, 256>>>(conv_w, conv_b, x_proj_w);

    // 6) dt_proj + softplus -> g_deltat
    gemm_nt4<<<dim3(DINNER / 64, MROWS / 64), 256>>>(dt_proj_w, dt_proj_b);

    // 7-9) chunked selective scan
    scan_phaseA<<<dim3(NCHAN / 128, TCHUNK), 128>>>(A_log);
    scan_phaseB<<<NCHAN * DSTATE / 256, 256>>>();
    scan_phaseC<<<dim3(NCHAN / 128, TCHUNK), 128>>>(A_log, D_param);

    // 10) out_proj (tf32 mma, 128x64 tile) -> out
    gemm_tf<6, 64><<<dim3(DMODEL / 64, MROWS / 128), 256, GTF_SMEM(64)>>>(out);
}

// round 16
// speedup vs baseline: 1.0121x; 1.0121x over previous
#include <cuda_runtime.h>
#include <cuda_bf16.h>
#include <cstdint>

// ---------------------------------------------------------------------------
// Mamba block forward.  B=2, L=2048, d_model=512, d_inner=1024, d_state=16,
// dt_rank=32, d_conv=4.
// Launches: 1 cvt_all     x / in_proj_w / out_proj_w -> tf32 (one kernel)
//           2 gemm_tf<1,128> in_proj (tf32 mma, ldmatrix)
//           3 conv_xproj  conv+silu + x_proj fused
//           4 gemm_nt4    dt_proj + softplus -> delta_t
//           5-7 scan A/B/C chunked selective scan (thread-per-channel)
//           8 gemm_tf<6,64> out_proj
// ---------------------------------------------------------------------------

#define BATCH    2
#define SEQLEN   2048
#define DMODEL   512
#define DINNER   1024
#define DSTATE   16
#define DTRANK   32
#define DCONV    4
#define MROWS    (BATCH * SEQLEN)        // 4096
#define NCHAN    (BATCH * DINNER)        // 2048 scan channels
#define TCHUNK   32                      // scan chunks along L
#define CLEN     (SEQLEN / TCHUNK)       // 64 steps per chunk

// Scratch (device-global; no runtime allocation allowed)
__device__ float g_xz[(size_t)MROWS * 2 * DINNER];    // [4096, 2048]  xs | z
__device__ float g_xst[(size_t)NCHAN * SEQLEN];       // xs transposed [ch][l]
__device__ float g_zt[(size_t)NCHAN * SEQLEN];        // z transposed [ch][l]
__device__ float g_xdbl[(size_t)MROWS * 64];          // [4096, 64]
__device__ float g_deltat[(size_t)NCHAN * SEQLEN];    // delta transposed [ch][l]
__device__ float g_y[(size_t)MROWS * DINNER];         // scan output (tf32-rounded)
__device__ uint32_t g_w6tf[(size_t)DMODEL * DINNER];  // out_proj_w in tf32
__device__ uint32_t g_x1tf[(size_t)MROWS * DMODEL];   // x in tf32
__device__ uint32_t g_w1tf[(size_t)2 * DINNER * DMODEL]; // in_proj_w in tf32
__device__ float g_hend[(size_t)TCHUNK * NCHAN * DSTATE];
__device__ float g_decay[(size_t)TCHUNK * NCHAN * DSTATE];
__device__ float g_h0[(size_t)TCHUNK * NCHAN * DSTATE];

// ---------------------------------------------------------------------------
__device__ __forceinline__ uint32_t f2tf32(float f) {
    uint32_t r;
    asm("cvt.rna.tf32.f32 %0, %1;" : "=r"(r) : "f"(f));
    return r;
}

__device__ __forceinline__ void mma_tf32(float c[4], const uint32_t a[4],
                                         uint32_t b0, uint32_t b1) {
    asm volatile(
        "mma.sync.aligned.m16n8k8.row.col.f32.tf32.tf32.f32 "
        "{%0,%1,%2,%3}, {%4,%5,%6,%7}, {%8,%9}, {%0,%1,%2,%3};"
        : "+f"(c[0]), "+f"(c[1]), "+f"(c[2]), "+f"(c[3])
        : "r"(a[0]), "r"(a[1]), "r"(a[2]), "r"(a[3]), "r"(b0), "r"(b1));
}

__device__ __forceinline__ void ldsm_x4(uint32_t r[4], uint32_t addr) {
    asm volatile(
        "ldmatrix.sync.aligned.m8n8.x4.shared.b16 {%0,%1,%2,%3}, [%4];"
        : "=r"(r[0]), "=r"(r[1]), "=r"(r[2]), "=r"(r[3]) : "r"(addr));
}

__device__ __forceinline__ void cp16(uint32_t dst_smem, const void* src) {
    asm volatile("cp.async.cg.shared.global [%0], [%1], 16;\n"
                 :: "r"(dst_smem), "l"(src));
}

// ---------------------------------------------------------------------------
// Prepass (single kernel): x (2M) + in_proj_w (1M) + out_proj_w (0.5M) -> tf32.
// 3.5M floats, float4 per thread, grid-strided over the three regions.
// ---------------------------------------------------------------------------
__global__ void __launch_bounds__(256)
cvt_all(const float* __restrict__ x, const float* __restrict__ in_proj_w,
        const float* __restrict__ out_proj_w)
{
    constexpr size_t NX = (size_t)MROWS * DMODEL;            // 2M
    constexpr size_t NW1 = (size_t)2 * DINNER * DMODEL;      // 1M
    constexpr size_t NW6 = (size_t)DMODEL * DINNER;          // 0.5M
    const size_t i4 = ((size_t)blockIdx.x * 256 + threadIdx.x) * 4;
    const float* src;
    uint32_t* dst;
    size_t off;
    if (i4 < NX)            { src = x;          dst = g_x1tf; off = i4; }
    else if (i4 < NX + NW1) { src = in_proj_w;  dst = g_w1tf; off = i4 - NX; }
    else                    { src = out_proj_w; dst = g_w6tf; off = i4 - NX - NW1; }
    float4 v = *(const float4*)&src[off];
    uint4 p;
    p.x = f2tf32(v.x); p.y = f2tf32(v.y);
    p.z = f2tf32(v.z); p.w = f2tf32(v.w);
    *(uint4*)&dst[off] = p;
}

// ---------------------------------------------------------------------------
// tf32 mma NT GEMM, BK=32 SW128 swizzle, 3-stage cp.async, ldmatrix fragments.
// R14 ordering: fill(c+2) issued AFTER compute(c).  Fill addressing hoisted.
//   STAGE 1 (BN=128): A=g_x1tf, W=g_w1tf, C=g_xz, K=512,  ldc=2048
//   STAGE 6 (BN=64):  A=g_y,    W=g_w6tf, C=out,  K=1024, ldc=512
// ---------------------------------------------------------------------------
#define GTF_SMEM(BN) (1024 + 3 * ((128 + (BN)) * 128))

template <int STAGE, int BN>
__global__ void __launch_bounds__(256)
gemm_tf(float* __restrict__ Cp)
{
    constexpr int K   = (STAGE == 1) ? DMODEL : DINNER;
    constexpr int ldc = (STAGE == 1) ? 2 * DINNER : DMODEL;
    constexpr int NC  = K / 32;                        // 32-K chunks
    constexpr int JN  = BN / 16;                       // n atoms per warp
    constexpr int J2  = JN / 2;                        // ldmatrix pairs
    constexpr int NBT = BN / 32;                       // B row-tiles per fill
    constexpr int ASZ = 128 * 32;                      // u32 per A stage
    constexpr int BSZ = BN * 32;                       // u32 per B stage

    const uint32_t* Ab = (STAGE == 1) ? g_x1tf : (const uint32_t*)g_y;
    const uint32_t* Wb = (STAGE == 1) ? g_w1tf : g_w6tf;
    float* C = (STAGE == 1) ? g_xz : Cp;

    extern __shared__ char dsm[];
    uint32_t* sbase = (uint32_t*)(((uintptr_t)dsm + 1023) & ~(uintptr_t)1023);
    uint32_t* const SA = sbase;                        // 3 x ASZ
    uint32_t* const SB = sbase + 3 * ASZ;              // 3 x BSZ
    const uint32_t saB = (uint32_t)__cvta_generic_to_shared(SA);
    const uint32_t sbB = (uint32_t)__cvta_generic_to_shared(SB);

    const int tid = threadIdx.x;
    const int lane = tid & 31;
    const int wid = tid >> 5;
    const int wm = (wid & 3) * 32;
    const int wn = (wid >> 2) * (BN / 2);
    const int g  = lane >> 2;
    const int tg = lane & 3;
    const int m0 = blockIdx.y * 128;
    const int n0 = blockIdx.x * BN;

    // ldmatrix per-lane addressing
    const int mi = lane >> 3;
    const int rr = lane & 7;
    uint32_t aRow[2];
#pragma unroll
    for (int i = 0; i < 2; i++)
        aRow[i] = (uint32_t)((wm + i * 16 + ((mi & 1) << 3) + rr) * 32);
    const int qaB = mi >> 1;
    uint32_t bRow[J2];
#pragma unroll
    for (int j2 = 0; j2 < J2; j2++)
        bRow[j2] = (uint32_t)((wn + j2 * 16 + ((mi >> 1) << 3) + rr) * 32);
    const int qbB = mi & 1;

    // hoisted fill addressing
    const int fcs = tid & 7;
    const int fr0 = tid >> 3;                          // 0..31
    const uint32_t* gA[4];
    uint32_t offA[4];
#pragma unroll
    for (int it = 0; it < 4; it++) {
        const int r = fr0 + it * 32;
        gA[it] = Ab + (size_t)(m0 + r) * K + fcs * 4;
        offA[it] = (uint32_t)(r * 32 + ((fcs ^ (r & 7)) << 2)) * 4;
    }
    const uint32_t* gB[NBT];
    uint32_t offB[NBT];
#pragma unroll
    for (int it = 0; it < NBT; it++) {
        const int r = fr0 + it * 32;
        gB[it] = Wb + (size_t)(n0 + r) * K + fcs * 4;
        offB[it] = (uint32_t)(r * 32 + ((fcs ^ (r & 7)) << 2)) * 4;
    }

    auto fill = [&](int st, int kc) {
        const uint32_t sa = saB + (uint32_t)(st * ASZ * 4);
        const uint32_t sb = sbB + (uint32_t)(st * BSZ * 4);
        const int k0 = kc * 32;
#pragma unroll
        for (int it = 0; it < 4; it++)
            cp16(sa + offA[it], gA[it] + k0);
#pragma unroll
        for (int it = 0; it < NBT; it++)
            cp16(sb + offB[it], gB[it] + k0);
    };

    float c[2][JN][4];
#pragma unroll
    for (int i = 0; i < 2; i++)
#pragma unroll
        for (int j = 0; j < JN; j++)
#pragma unroll
            for (int r = 0; r < 4; r++) c[i][j][r] = 0.f;

    fill(0, 0); asm volatile("cp.async.commit_group;\n" ::);
    fill(1, 1); asm volatile("cp.async.commit_group;\n" ::);

#pragma unroll 1
    for (int cchunk = 0; cchunk < NC; cchunk++) {
        const int s = cchunk % 3;
        if (cchunk + 1 < NC) asm volatile("cp.async.wait_group 1;\n" ::);
        else                 asm volatile("cp.async.wait_group 0;\n" ::);
        __syncthreads();

        const uint32_t saS = saB + (uint32_t)(s * ASZ * 4);
        const uint32_t sbS = sbB + (uint32_t)(s * BSZ * 4);
#pragma unroll
        for (int kk = 0; kk < 4; kk++) {               // 4 x K=8 per chunk
            const int q0 = kk * 2;
            uint32_t a[2][4];
#pragma unroll
            for (int i = 0; i < 2; i++) {
                const uint32_t q = (uint32_t)(q0 + qaB);
                ldsm_x4(a[i], saS + (aRow[i] + (((q ^ (uint32_t)rr)) << 2)) * 4);
            }
            uint32_t bf[JN][2];
#pragma unroll
            for (int j2 = 0; j2 < J2; j2++) {
                const uint32_t q = (uint32_t)(q0 + qbB);
                uint32_t t[4];
                ldsm_x4(t, sbS + (bRow[j2] + (((q ^ (uint32_t)rr)) << 2)) * 4);
                bf[2 * j2][0] = t[0]; bf[2 * j2][1] = t[1];
                bf[2 * j2 + 1][0] = t[2]; bf[2 * j2 + 1][1] = t[3];
            }
#pragma unroll
            for (int j = 0; j < JN; j++) {
                mma_tf32(c[0][j], a[0], bf[j][0], bf[j][1]);
                mma_tf32(c[1][j], a[1], bf[j][0], bf[j][1]);
            }
        }

        if (cchunk + 2 < NC) {
            fill((cchunk + 2) % 3, cchunk + 2);
            asm volatile("cp.async.commit_group;\n" ::);
        }
    }

    // epilogue
#pragma unroll
    for (int i = 0; i < 2; i++) {
        const int mrow0 = m0 + wm + i * 16 + g;
#pragma unroll
        for (int j = 0; j < JN; j++) {
            const int ncol = n0 + wn + j * 8 + 2 * tg;
            *(float2*)&C[(size_t)mrow0 * ldc + ncol] =
                make_float2(c[i][j][0], c[i][j][1]);
            *(float2*)&C[(size_t)(mrow0 + 8) * ldc + ncol] =
                make_float2(c[i][j][2], c[i][j][3]);
        }
    }
}

// ---------------------------------------------------------------------------
// Stage 2+3 fused: conv1d+SiLU, x_proj GEMM; writes xs_t and z_t transposed.
// ---------------------------------------------------------------------------
__global__ void __launch_bounds__(256)
conv_xproj(const float* __restrict__ conv_w,
           const float* __restrict__ conv_b,
           const float* __restrict__ x_proj_w)
{
    __shared__ float sxs[32][68];
    __shared__ float sw[64][68];
    __shared__ float sz[32][68];

    const int tid = threadIdx.x;
    const int bl0 = blockIdx.x * 32;
    const int b   = bl0 >> 11;
    const int l0  = bl0 & 2047;
    const int tx = tid & 15;
    const int ty = tid >> 4;

    float acc[2][4];
#pragma unroll
    for (int i = 0; i < 2; i++)
#pragma unroll
        for (int j = 0; j < 4; j++) acc[i][j] = 0.f;

#pragma unroll 1
    for (int d0 = 0; d0 < DINNER; d0 += 64) {
        __syncthreads();
#pragma unroll
        for (int it = 0; it < 4; it++) {
            const int idx = tid + it * 256;
            const int e = idx >> 4, c4 = (idx & 15) * 4;
            *(float4*)&sw[e][c4] =
                *(const float4*)&x_proj_w[(size_t)e * DINNER + d0 + c4];
        }
#pragma unroll
        for (int it = 0; it < 8; it++) {
            const int idx = tid + it * 256;
            const int r = idx >> 6, dc = idx & 63;
            const int bl = bl0 + r;
            const int l = bl & (SEQLEN - 1);
            const int d = d0 + dc;
            float a = conv_b[d];
#pragma unroll
            for (int j = 0; j < DCONV; j++) {
                const int ls = l - (DCONV - 1) + j;
                if (ls >= 0)
                    a = fmaf(g_xz[(size_t)(bl - (DCONV - 1) + j) * (2 * DINNER) + d],
                             conv_w[d * DCONV + j], a);
            }
            sxs[r][dc] = a / (1.f + __expf(-a));     // SiLU
            sz[r][dc] = g_xz[(size_t)bl * (2 * DINNER) + DINNER + d];
        }
        __syncthreads();
        {
            const int dloc = tid >> 2;
            const int lq = (tid & 3) * 8;
            const size_t row = (size_t)(b * DINNER + d0 + dloc) * SEQLEN + l0 + lq;
            float4 v0, v1;
            v0.x = sxs[lq + 0][dloc]; v0.y = sxs[lq + 1][dloc];
            v0.z = sxs[lq + 2][dloc]; v0.w = sxs[lq + 3][dloc];
            v1.x = sxs[lq + 4][dloc]; v1.y = sxs[lq + 5][dloc];
            v1.z = sxs[lq + 6][dloc]; v1.w = sxs[lq + 7][dloc];
            *(float4*)&g_xst[row] = v0;
            *(float4*)&g_xst[row + 4] = v1;
            v0.x = sz[lq + 0][dloc]; v0.y = sz[lq + 1][dloc];
            v0.z = sz[lq + 2][dloc]; v0.w = sz[lq + 3][dloc];
            v1.x = sz[lq + 4][dloc]; v1.y = sz[lq + 5][dloc];
            v1.z = sz[lq + 6][dloc]; v1.w = sz[lq + 7][dloc];
            *(float4*)&g_zt[row] = v0;
            *(float4*)&g_zt[row + 4] = v1;
        }
#pragma unroll
        for (int kk = 0; kk < 64; kk++) {
            float ar[2], br[4];
#pragma unroll
            for (int i = 0; i < 2; i++) ar[i] = sxs[ty * 2 + i][kk];
#pragma unroll
            for (int j = 0; j < 4; j++) br[j] = sw[tx * 4 + j][kk];
#pragma unroll
            for (int i = 0; i < 2; i++)
#pragma unroll
                for (int j = 0; j < 4; j++)
                    acc[i][j] = fmaf(ar[i], br[j], acc[i][j]);
        }
    }

#pragma unroll
    for (int i = 0; i < 2; i++)
#pragma unroll
        for (int j = 0; j < 4; j++)
            g_xdbl[(size_t)(bl0 + ty * 2 + i) * 64 + tx * 4 + j] = acc[i][j];
}

// ---------------------------------------------------------------------------
// Stage 4: dt_proj + softplus -> delta_t[ch][l] (transposed write).
// ---------------------------------------------------------------------------
__global__ void __launch_bounds__(256)
gemm_nt4(const float* __restrict__ W, const float* __restrict__ bias)
{
    constexpr int BM = 64, BN = 64, BK = 16;
    constexpr int lda = 64, ldw = DTRANK, K = DTRANK;
    const float* A = g_xdbl;

    __shared__ float As[BK][BM];
    __shared__ float Bs[BK][BN];

    const int tid = threadIdx.x;
    const int m0 = blockIdx.y * BM;
    const int n0 = blockIdx.x * BN;
    const int tx = tid & 15;
    const int ty = tid >> 4;
    const int lrow = tid >> 2;
    const int lc4 = (tid & 3) * 4;

    float acc[4][4];
#pragma unroll
    for (int i = 0; i < 4; i++)
#pragma unroll
        for (int j = 0; j < 4; j++) acc[i][j] = 0.f;

    const float* Arow = A + (size_t)(m0 + lrow) * lda + lc4;
    const float* Wrow = W + (size_t)(n0 + lrow) * ldw + lc4;

#pragma unroll 1
    for (int k0 = 0; k0 < K; k0 += BK) {
        float4 av = *(const float4*)(Arow + k0);
        float4 wv = *(const float4*)(Wrow + k0);
        __syncthreads();
        As[lc4 + 0][lrow] = av.x; As[lc4 + 1][lrow] = av.y;
        As[lc4 + 2][lrow] = av.z; As[lc4 + 3][lrow] = av.w;
        Bs[lc4 + 0][lrow] = wv.x; Bs[lc4 + 1][lrow] = wv.y;
        Bs[lc4 + 2][lrow] = wv.z; Bs[lc4 + 3][lrow] = wv.w;
        __syncthreads();
#pragma unroll
        for (int kk = 0; kk < BK; kk++) {
            float4 a4 = *(const float4*)&As[kk][ty * 4];
            float4 b4 = *(const float4*)&Bs[kk][tx * 4];
            float ar[4] = {a4.x, a4.y, a4.z, a4.w};
            float br[4] = {b4.x, b4.y, b4.z, b4.w};
#pragma unroll
            for (int i = 0; i < 4; i++)
#pragma unroll
                for (int j = 0; j < 4; j++)
                    acc[i][j] = fmaf(ar[i], br[j], acc[i][j]);
        }
    }

    const int b = m0 >> 11;
    const int lb = (m0 & 2047) + ty * 4;
#pragma unroll
    for (int j = 0; j < 4; j++) {
        const int n = n0 + tx * 4 + j;
        float sp[4];
#pragma unroll
        for (int i = 0; i < 4; i++) {
            float v = acc[i][j] + bias[n];
            sp[i] = (v > 20.f) ? v : log1pf(__expf(v));
        }
        *(float4*)&g_deltat[(size_t)(b * DINNER + n) * SEQLEN + lb] =
            make_float4(sp[0], sp[1], sp[2], sp[3]);
    }
}

// ---------------------------------------------------------------------------
// Scan phase A: thread-per-channel; all 16 states in registers.
// ---------------------------------------------------------------------------
__global__ void __launch_bounds__(128)
scan_phaseA(const float* __restrict__ A_log)
{
    const int tid = threadIdx.x;
    const int ch = blockIdx.x * 128 + tid;     // global channel
    const int t  = blockIdx.y;
    const int b  = ch >> 10;
    const int d  = ch & (DINNER - 1);

    float A_dn[DSTATE];
#pragma unroll
    for (int q = 0; q < 4; q++) {
        float4 a4 = *(const float4*)&A_log[d * DSTATE + q * 4];
        A_dn[q * 4 + 0] = -__expf(a4.x);
        A_dn[q * 4 + 1] = -__expf(a4.y);
        A_dn[q * 4 + 2] = -__expf(a4.z);
        A_dn[q * 4 + 3] = -__expf(a4.w);
    }

    const float* dl = g_deltat + (size_t)ch * SEQLEN + t * CLEN;
    const float* us = g_xst    + (size_t)ch * SEQLEN + t * CLEN;
    const float* xb = g_xdbl + ((size_t)b * SEQLEN + t * CLEN) * 64 + 32;

    float h[DSTATE];
#pragma unroll
    for (int n = 0; n < DSTATE; n++) h[n] = 0.f;
    float sdt = 0.f;

#pragma unroll 1
    for (int l4 = 0; l4 < CLEN; l4 += 4) {
        const float4 d4 = *(const float4*)(dl + l4);
        const float4 u4 = *(const float4*)(us + l4);
        const float dts[4] = {d4.x, d4.y, d4.z, d4.w};
        const float uus[4] = {u4.x, u4.y, u4.z, u4.w};
#pragma unroll
        for (int j = 0; j < 4; j++) {
            const float4* Bp = (const float4*)(xb + (size_t)(l4 + j) * 64);
            float Bv[DSTATE];
#pragma unroll
            for (int q = 0; q < 4; q++) {
                float4 v = Bp[q];
                Bv[q * 4 + 0] = v.x; Bv[q * 4 + 1] = v.y;
                Bv[q * 4 + 2] = v.z; Bv[q * 4 + 3] = v.w;
            }
            const float dt = dts[j];
            const float dtu = dt * uus[j];
            sdt += dt;
#pragma unroll
            for (int n = 0; n < DSTATE; n++) {
                const float dA = __expf(dt * A_dn[n]);
                h[n] = fmaf(dA, h[n], dtu * Bv[n]);
            }
        }
    }

    float* he = g_hend  + ((size_t)t * NCHAN + ch) * DSTATE;
    float* de = g_decay + ((size_t)t * NCHAN + ch) * DSTATE;
#pragma unroll
    for (int q = 0; q < 4; q++)
        *(float4*)(he + q * 4) =
            make_float4(h[q * 4], h[q * 4 + 1], h[q * 4 + 2], h[q * 4 + 3]);
#pragma unroll
    for (int q = 0; q < 4; q++) {
        float4 v;
        v.x = __expf(sdt * A_dn[q * 4 + 0]);
        v.y = __expf(sdt * A_dn[q * 4 + 1]);
        v.z = __expf(sdt * A_dn[q * 4 + 2]);
        v.w = __expf(sdt * A_dn[q * 4 + 3]);
        *(float4*)(de + q * 4) = v;
    }
}

// ---------------------------------------------------------------------------
// Scan phase B: compose chunk states serially over T chunks.
// ---------------------------------------------------------------------------
__global__ void __launch_bounds__(256)
scan_phaseB()
{
    const int id = blockIdx.x * 256 + threadIdx.x;   // 0..NCHAN*DSTATE-1
    float h = 0.f;
#pragma unroll
    for (int t = 0; t < TCHUNK; t++) {
        const size_t o = (size_t)t * NCHAN * DSTATE + id;
        g_h0[o] = h;
        h = g_decay[o] * h + g_hend[o];
    }
}

// ---------------------------------------------------------------------------
// Scan phase C: thread-per-channel full scan from h0 -> y (no shfl).
// ---------------------------------------------------------------------------
__global__ void __launch_bounds__(128)
scan_phaseC(const float* __restrict__ A_log,
            const float* __restrict__ D_param)
{
    const int tid = threadIdx.x;
    const int ch = blockIdx.x * 128 + tid;
    const int t  = blockIdx.y;
    const int b  = ch >> 10;
    const int d  = ch & (DINNER - 1);

    float A_dn[DSTATE];
#pragma unroll
    for (int q = 0; q < 4; q++) {
        float4 a4 = *(const float4*)&A_log[d * DSTATE + q * 4];
        A_dn[q * 4 + 0] = -__expf(a4.x);
        A_dn[q * 4 + 1] = -__expf(a4.y);
        A_dn[q * 4 + 2] = -__expf(a4.z);
        A_dn[q * 4 + 3] = -__expf(a4.w);
    }
    const float Dd = D_param[d];

    const float* dl = g_deltat + (size_t)ch * SEQLEN + t * CLEN;
    const float* us = g_xst    + (size_t)ch * SEQLEN + t * CLEN;
    const float* zp = g_zt     + (size_t)ch * SEQLEN + t * CLEN;
    const float* xr = g_xdbl + ((size_t)b * SEQLEN + t * CLEN) * 64;
    float* yp = g_y + ((size_t)b * SEQLEN + t * CLEN) * DINNER + d;

    float h[DSTATE];
    {
        const float* h0 = g_h0 + ((size_t)t * NCHAN + ch) * DSTATE;
#pragma unroll
        for (int q = 0; q < 4; q++) {
            float4 v = *(const float4*)(h0 + q * 4);
            h[q * 4 + 0] = v.x; h[q * 4 + 1] = v.y;
            h[q * 4 + 2] = v.z; h[q * 4 + 3] = v.w;
        }
    }

#pragma unroll 1
    for (int l4 = 0; l4 < CLEN; l4 += 4) {
        const float4 d4 = *(const float4*)(dl + l4);
        const float4 u4 = *(const float4*)(us + l4);
        const float4 z4 = *(const float4*)(zp + l4);
        const float dts[4] = {d4.x, d4.y, d4.z, d4.w};
        const float uus[4] = {u4.x, u4.y, u4.z, u4.w};
        const float zzs[4] = {z4.x, z4.y, z4.z, z4.w};
#pragma unroll
        for (int j = 0; j < 4; j++) {
            const float4* Rp = (const float4*)(xr + (size_t)(l4 + j) * 64 + 32);
            float Bv[DSTATE], Cv[DSTATE];
#pragma unroll
            for (int q = 0; q < 4; q++) {
                float4 v = Rp[q];
                Bv[q * 4 + 0] = v.x; Bv[q * 4 + 1] = v.y;
                Bv[q * 4 + 2] = v.z; Bv[q * 4 + 3] = v.w;
                float4 w = Rp[q + 4];
                Cv[q * 4 + 0] = w.x; Cv[q * 4 + 1] = w.y;
                Cv[q * 4 + 2] = w.z; Cv[q * 4 + 3] = w.w;
            }
            const float dt = dts[j];
            const float dtu = dt * uus[j];
            float y = 0.f;
#pragma unroll
            for (int n = 0; n < DSTATE; n++) {
                const float dA = __expf(dt * A_dn[n]);
                h[n] = fmaf(dA, h[n], dtu * Bv[n]);
                y = fmaf(h[n], Cv[n], y);
            }
            const float z = zzs[j];
            const float sz = z / (1.f + __expf(-z));
            const float v = (y + uus[j] * Dd) * sz;
            yp[(size_t)(l4 + j) * DINNER] = __uint_as_float(f2tf32(v));
        }
    }
}

// ---------------------------------------------------------------------------
extern "C" void kernel_launch(void* const* d_in, const int* in_sizes, int n_in,
                              void* d_out, int out_size)
{
    const float* x          = (const float*)d_in[0];
    const float* in_proj_w  = (const float*)d_in[1];
    const float* conv_w     = (const float*)d_in[2];
    const float* conv_b     = (const float*)d_in[3];
    const float* x_proj_w   = (const float*)d_in[4];
    const float* dt_proj_w  = (const float*)d_in[5];
    const float* dt_proj_b  = (const float*)d_in[6];
    const float* A_log      = (const float*)d_in[7];
    const float* D_param    = (const float*)d_in[8];
    const float* out_proj_w = (const float*)d_in[9];
    float* out = (float*)d_out;

    cudaFuncSetAttribute((const void*)gemm_tf<1, 128>,
                         cudaFuncAttributeMaxDynamicSharedMemorySize, GTF_SMEM(128));
    cudaFuncSetAttribute((const void*)gemm_tf<6, 64>,
                         cudaFuncAttributeMaxDynamicSharedMemorySize, GTF_SMEM(64));

    // 1) tf32 prepass (x + in_proj_w + out_proj_w = 3.5M floats)
    cvt_all<<<(3 * 1024 * 1024 + 512 * 1024) / 1024, 256>>>(x, in_proj_w, out_proj_w);

    // 2) in_proj (tf32 mma, ldmatrix) -> g_xz
    gemm_tf<1, 128><<<dim3(2 * DINNER / 128, MROWS / 128), 256, GTF_SMEM(128)>>>(nullptr);

    // 3) conv+silu fused with x_proj -> g_xst, g_zt, g_xdbl
    conv_xproj<<<MROWS / 32, 256>>>(conv_w, conv_b, x_proj_w);

    // 4) dt_proj + softplus -> g_deltat
    gemm_nt4<<<dim3(DINNER / 64, MROWS / 64), 256>>>(dt_proj_w, dt_proj_b);

    // 5-7) chunked selective scan
    scan_phaseA<<<dim3(NCHAN / 128, TCHUNK), 128>>>(A_log);
    scan_phaseB<<<NCHAN * DSTATE / 256, 256>>>();
    scan_phaseC<<<dim3(NCHAN / 128, TCHUNK), 128>>>(A_log, D_param);

    // 8) out_proj (tf32 mma, 128x64 tile) -> out
    gemm_tf<6, 64><<<dim3(DMODEL / 64, MROWS / 128), 256, GTF_SMEM(64)>>>(out);
}